// round 3
// baseline (speedup 1.0000x reference)
#include <cuda_runtime.h>
#include <cstdint>

// TVConv: per-pixel spatially-varying 3x3 depthwise conv, zero padding.
// x:           (B=8, C=96, H=128, W=128) fp32
// weight_maps: (1,   C=96, 3, 3, H, W)   fp32  (batch-invariant!)
// out:         (B, C, H, W) fp32
//
// Strategy: each thread owns one (c, h, [w0..w0+3]) group. It loads the
// 9 taps' weights ONCE as float4s (amortized over all 8 batches), then
// loops b=0..7 loading a 3x6 x-window and producing a float4 output.
// This keeps DRAM traffic at the 157MB minimum (x + w + out each once).

namespace {
constexpr int B = 8;
constexpr int C = 96;
constexpr int H = 128;
constexpr int W = 128;
constexpr int W4 = W / 4;
constexpr int HW = H * W;
constexpr int NTHREADS_TOTAL = C * H * W4;  // 393216
}

__global__ __launch_bounds__(256) void tvconv_kernel(
    const float* __restrict__ x,
    const float* __restrict__ wm,
    float* __restrict__ out)
{
    int idx = blockIdx.x * blockDim.x + threadIdx.x;
    if (idx >= NTHREADS_TOTAL) return;

    int w4 = idx % W4;
    int t  = idx / W4;
    int h  = t % H;
    int c  = t / H;
    int w0 = w4 * 4;

    // ---- load 9 taps of weights for these 4 pixels (float4, aligned) ----
    const float* wbase = wm + (size_t)c * 9 * HW + (size_t)h * W + w0;
    float4 wt[9];
#pragma unroll
    for (int k = 0; k < 9; k++) {
        wt[k] = *reinterpret_cast<const float4*>(wbase + (size_t)k * HW);
    }

    const size_t chw_off = (size_t)c * HW + (size_t)h * W + w0;

    for (int b = 0; b < B; b++) {
        const float* xb = x + (size_t)b * C * HW + (size_t)c * HW;
        float a0 = 0.f, a1 = 0.f, a2 = 0.f, a3 = 0.f;

#pragma unroll
        for (int i = 0; i < 3; i++) {
            int hh = h + i - 1;
            if ((unsigned)hh < (unsigned)H) {
                const float* xrow = xb + (size_t)hh * W;
                // x window: columns w0-1 .. w0+4 (6 values), zero-padded
                float v[6];
#pragma unroll
                for (int j = 0; j < 6; j++) {
                    int ww = w0 - 1 + j;
                    v[j] = ((unsigned)ww < (unsigned)W) ? __ldg(xrow + ww) : 0.f;
                }
#pragma unroll
                for (int j = 0; j < 3; j++) {
                    float4 wk = wt[i * 3 + j];
                    a0 = fmaf(wk.x, v[j + 0], a0);
                    a1 = fmaf(wk.y, v[j + 1], a1);
                    a2 = fmaf(wk.z, v[j + 2], a2);
                    a3 = fmaf(wk.w, v[j + 3], a3);
                }
            }
        }

        float4 o = make_float4(a0, a1, a2, a3);
        *reinterpret_cast<float4*>(out + (size_t)b * C * HW + chw_off) = o;
    }
}

extern "C" void kernel_launch(void* const* d_in, const int* in_sizes, int n_in,
                              void* d_out, int out_size)
{
    const float* x  = (const float*)d_in[0];
    const float* wm = (const float*)d_in[1];
    float* out      = (float*)d_out;

    const int threads = 256;
    const int blocks  = (NTHREADS_TOTAL + threads - 1) / threads;  // 1536
    tvconv_kernel<<<blocks, threads>>>(x, wm, out);
}

// round 4
// speedup vs baseline: 1.4233x; 1.4233x over previous
#include <cuda_runtime.h>
#include <cstdint>

// TVConv: per-pixel spatially-varying 3x3 depthwise conv, zero padding.
// x:           (B=8, C=96, H=128, W=128) fp32
// weight_maps: (1,   C=96, 3, 3, H, W)   fp32  (batch-invariant)
// out:         (B, C, H, W) fp32
//
// R3->R4 change: a warp covers exactly one (c,h) row (32 lanes x 4 px = W).
// Each lane loads one aligned float4 per input row (3 LDG.128 per batch
// instead of 18 scalar LDG) and obtains the w0-1 / w0+4 halo values via
// warp shuffle. Horizontal zero-pad = lane-0/31 masking. This cuts L1tex
// wavefront traffic ~6x (it was the 61.6%-busy bottleneck) and widens
// memory requests, pushing the kernel toward the DRAM roofline.

namespace {
constexpr int B = 8;
constexpr int C = 96;
constexpr int H = 128;
constexpr int W = 128;
constexpr int W4 = W / 4;              // 32 == warp size
constexpr int HW = H * W;
constexpr int NTHREADS_TOTAL = C * H * W4;  // 393216
}

__device__ __forceinline__ void accum_row(
    float4 r, float4 k0, float4 k1, float4 k2,
    float& a0, float& a1, float& a2, float& a3, int lane)
{
    float left  = __shfl_up_sync(0xffffffffu,  r.w, 1);
    float right = __shfl_down_sync(0xffffffffu, r.x, 1);
    if (lane == 0)  left  = 0.f;   // w = -1  -> zero pad
    if (lane == 31) right = 0.f;   // w = 128 -> zero pad
    a0 = fmaf(k0.x, left, fmaf(k1.x, r.x, fmaf(k2.x, r.y, a0)));
    a1 = fmaf(k0.y, r.x,  fmaf(k1.y, r.y, fmaf(k2.y, r.z, a1)));
    a2 = fmaf(k0.z, r.y,  fmaf(k1.z, r.z, fmaf(k2.z, r.w, a2)));
    a3 = fmaf(k0.w, r.z,  fmaf(k1.w, r.w, fmaf(k2.w, right, a3)));
}

__global__ __launch_bounds__(256, 4) void tvconv_kernel(
    const float* __restrict__ x,
    const float* __restrict__ wm,
    float* __restrict__ out)
{
    int idx  = blockIdx.x * blockDim.x + threadIdx.x;
    int lane = idx & 31;               // == w4 (W4 == 32)
    int t    = idx >> 5;
    int h    = t % H;
    int c    = t / H;
    int w0   = lane * 4;

    // ---- 9 taps of weights for these 4 pixels, kept in registers,
    //      amortized over all 8 batches ----
    const float* wbase = wm + (size_t)c * 9 * HW + (size_t)h * W + w0;
    float4 wt[9];
#pragma unroll
    for (int k = 0; k < 9; k++)
        wt[k] = *reinterpret_cast<const float4*>(wbase + (size_t)k * HW);

    const size_t chw_off = (size_t)c * HW + (size_t)h * W + w0;
    const float4 zero4 = make_float4(0.f, 0.f, 0.f, 0.f);
    const bool has_up = (h > 0), has_dn = (h < H - 1);

#pragma unroll 2
    for (int b = 0; b < B; b++) {
        const float* xrow = x + ((size_t)b * C) * HW + chw_off;

        float4 r1 = *reinterpret_cast<const float4*>(xrow);
        float4 r0 = has_up ? *reinterpret_cast<const float4*>(xrow - W) : zero4;
        float4 r2 = has_dn ? *reinterpret_cast<const float4*>(xrow + W) : zero4;

        float a0 = 0.f, a1 = 0.f, a2 = 0.f, a3 = 0.f;
        accum_row(r0, wt[0], wt[1], wt[2], a0, a1, a2, a3, lane);
        accum_row(r1, wt[3], wt[4], wt[5], a0, a1, a2, a3, lane);
        accum_row(r2, wt[6], wt[7], wt[8], a0, a1, a2, a3, lane);

        *reinterpret_cast<float4*>(out + (size_t)b * C * HW + chw_off) =
            make_float4(a0, a1, a2, a3);
    }
}

extern "C" void kernel_launch(void* const* d_in, const int* in_sizes, int n_in,
                              void* d_out, int out_size)
{
    const float* x  = (const float*)d_in[0];
    const float* wm = (const float*)d_in[1];
    float* out      = (float*)d_out;

    const int threads = 256;
    const int blocks  = NTHREADS_TOTAL / threads;  // 1536
    tvconv_kernel<<<blocks, threads>>>(x, wm, out);
}